// round 11
// baseline (speedup 1.0000x reference)
#include <cuda_runtime.h>
#include <cuda_bf16.h>

// ---------------------------------------------------------------------------
// BSAM self-attention via mma.sync bf16 (split precision), fp32 conv front.
//   Q = conv3x3(A1_B, w1*log2e, b1*log2e) -> g_Qs [b][p][hi32|lo32] bf16
//   K = conv3x3(A1_C, w2,b2)              -> g_Ks [b][p][hi32|lo32] bf16
//   V = conv3x3(A1_C, w3,b3)              -> g_V  [b][p][64] bf16
//   O = softmax2(Q^T K) V ; out = O^T + A1_C   (base-2 softmax, bias 51)
// R10: attention re-tiled to 2-warp / 32-query CTAs (512 blocks) so ~6 CTAs
//      coexist per SM and desynchronized chunk loops keep HMMA fed.
// ---------------------------------------------------------------------------

#define NB   4
#define NC   64
#define HW   64
#define NPIX 4096

typedef unsigned long long u64;
typedef unsigned u32;

__device__ __align__(16) __nv_bfloat16 g_Qs[NB * NPIX * 64];
__device__ __align__(16) __nv_bfloat16 g_Ks[NB * NPIX * 64];
__device__ __align__(16) __nv_bfloat16 g_V [NB * NPIX * 64];
__device__ __align__(16) float g_wpack[64 * 9 * 128];
__device__ __align__(16) float g_bias[128];

// ---- packed f32x2 helpers (conv) -------------------------------------------
__device__ __forceinline__ u64 ffma2(u64 a, u64 b, u64 c) {
    u64 d; asm("fma.rn.f32x2 %0, %1, %2, %3;" : "=l"(d) : "l"(a), "l"(b), "l"(c));
    return d;
}
__device__ __forceinline__ u64 fpack2(float lo, float hi) {
    u64 d; asm("mov.b64 %0, {%1, %2};" : "=l"(d) : "f"(lo), "f"(hi));
    return d;
}
__device__ __forceinline__ float2 funpack2(u64 v) {
    float2 r; asm("mov.b64 {%0, %1}, %2;" : "=f"(r.x), "=f"(r.y) : "l"(v));
    return r;
}
__device__ __forceinline__ float ex2f(float x) {
    float y; asm("ex2.approx.f32 %0, %1;" : "=f"(y) : "f"(x));
    return y;
}

// ---- cp.async / mma / ldmatrix ----------------------------------------------
__device__ __forceinline__ void cp_async16(void* sdst, const void* gsrc) {
    u32 sa = (u32)__cvta_generic_to_shared(sdst);
    asm volatile("cp.async.cg.shared.global [%0], [%1], 16;" :: "r"(sa), "l"(gsrc));
}
#define CP_COMMIT() asm volatile("cp.async.commit_group;")
#define CP_WAIT0()  asm volatile("cp.async.wait_group 0;")

__device__ __forceinline__ void mma_bf16(float& c0, float& c1, float& c2, float& c3,
                                         u32 a0, u32 a1, u32 a2, u32 a3,
                                         u32 b0, u32 b1) {
    asm volatile(
        "mma.sync.aligned.m16n8k16.row.col.f32.bf16.bf16.f32 "
        "{%0,%1,%2,%3}, {%4,%5,%6,%7}, {%8,%9}, {%0,%1,%2,%3};"
        : "+f"(c0), "+f"(c1), "+f"(c2), "+f"(c3)
        : "r"(a0), "r"(a1), "r"(a2), "r"(a3), "r"(b0), "r"(b1));
}
__device__ __forceinline__ void ldsm4(u32* r, u32 saddr) {
    asm volatile("ldmatrix.sync.aligned.m8n8.x4.shared.b16 {%0,%1,%2,%3}, [%4];"
        : "=r"(r[0]), "=r"(r[1]), "=r"(r[2]), "=r"(r[3]) : "r"(saddr));
}
__device__ __forceinline__ void ldsm4t(u32* r, u32 saddr) {
    asm volatile("ldmatrix.sync.aligned.m8n8.x4.trans.shared.b16 {%0,%1,%2,%3}, [%4];"
        : "=r"(r[0]), "=r"(r[1]), "=r"(r[2]), "=r"(r[3]) : "r"(saddr));
}
__device__ __forceinline__ u32 bf2u(__nv_bfloat162 h) {
    return *reinterpret_cast<u32*>(&h);
}

// ---------------------------------------------------------------------------
// Weight repack. co 0..31 = w1*log2e (Q), 32..63 = w2, 64..127 = w3
// ---------------------------------------------------------------------------
#define LOG2E 1.4426950408889634f

__global__ void pack_kernel(const float* __restrict__ w1, const float* __restrict__ b1,
                            const float* __restrict__ w2, const float* __restrict__ b2,
                            const float* __restrict__ w3, const float* __restrict__ b3) {
    int idx = blockIdx.x * 256 + threadIdx.x;
    if (idx < 128)
        g_bias[idx] = (idx < 32) ? b1[idx] * LOG2E
                    : (idx < 64) ? b2[idx - 32] : b3[idx - 64];
    if (idx < 64 * 9 * 128) {
        int co = idx & 127;
        int t  = idx >> 7;
        int ci = t / 9;
        int k  = t % 9;
        float v;
        if (co < 32)       v = w1[(co * 64 + ci) * 9 + k] * LOG2E;
        else if (co < 64)  v = w2[((co - 32) * 64 + ci) * 9 + k];
        else               v = w3[((co - 64) * 64 + ci) * 9 + k];
        g_wpack[idx] = v;
    }
}

// ---------------------------------------------------------------------------
// Conv (unchanged from R8): block=(row y, batch b), 128 thr, 2 pixels/thread.
// ---------------------------------------------------------------------------
#define CONV_SMEM (2 * 64 * 3 * 66 * 4)

__global__ __launch_bounds__(128)
void conv_kernel(const float* __restrict__ A1B, const float* __restrict__ A1C) {
    extern __shared__ float smem[];
    float* sB = smem;
    float* sC = smem + 64 * 3 * 66;

    const int y   = blockIdx.x;
    const int b   = blockIdx.y;
    const int tid = threadIdx.x;

    for (int idx = tid; idx < 64 * 3 * 66; idx += 128) {
        int ci  = idx / 198;
        int rem = idx % 198;
        int r   = rem / 66;
        int xx  = rem % 66;
        int yy  = y + r - 1;
        int x   = xx - 1;
        bool ok = (yy >= 0) && (yy < HW) && (x >= 0) && (x < HW);
        float vb = 0.f, vc = 0.f;
        if (ok) {
            int gi = ((b * 64 + ci) * HW + yy) * HW + x;
            vb = __ldg(A1B + gi);
            vc = __ldg(A1C + gi);
        }
        sB[idx] = vb;
        sC[idx] = vc;
    }
    __syncthreads();

    const int x0 = tid & 31;
    const int x1 = x0 + 32;
    const int g  = tid >> 5;
    const float* sIn = (g == 0) ? sB : sC;

    #pragma unroll
    for (int pass = 0; pass < 2; ++pass) {
        const int co0 = g * 32 + pass * 16;
        const u64* bp = reinterpret_cast<const u64*>(g_bias + co0);
        u64 acc0[8], acc1[8];
        #pragma unroll
        for (int u = 0; u < 8; ++u) { acc0[u] = bp[u]; acc1[u] = bp[u]; }

        for (int ci = 0; ci < 64; ++ci) {
            #pragma unroll
            for (int dy = 0; dy < 3; ++dy) {
                const float* row = sIn + (ci * 3 + dy) * 66;
                float a0 = row[x0], a1 = row[x0 + 1], a2 = row[x0 + 2];
                float c0 = row[x1], c1 = row[x1 + 1], c2 = row[x1 + 2];
                #pragma unroll
                for (int dx = 0; dx < 3; ++dx) {
                    float ivA = (dx == 0) ? a0 : (dx == 1) ? a1 : a2;
                    float ivB = (dx == 0) ? c0 : (dx == 1) ? c1 : c2;
                    u64 iA = fpack2(ivA, ivA);
                    u64 iB = fpack2(ivB, ivB);
                    const ulonglong2* wq = reinterpret_cast<const ulonglong2*>(
                        g_wpack + ((ci * 3 + dy) * 3 + dx) * 128 + co0);
                    ulonglong2 wA = __ldg(wq + 0);
                    ulonglong2 wB = __ldg(wq + 1);
                    ulonglong2 wC = __ldg(wq + 2);
                    ulonglong2 wD = __ldg(wq + 3);
                    acc0[0] = ffma2(iA, wA.x, acc0[0]); acc1[0] = ffma2(iB, wA.x, acc1[0]);
                    acc0[1] = ffma2(iA, wA.y, acc0[1]); acc1[1] = ffma2(iB, wA.y, acc1[1]);
                    acc0[2] = ffma2(iA, wB.x, acc0[2]); acc1[2] = ffma2(iB, wB.x, acc1[2]);
                    acc0[3] = ffma2(iA, wB.y, acc0[3]); acc1[3] = ffma2(iB, wB.y, acc1[3]);
                    acc0[4] = ffma2(iA, wC.x, acc0[4]); acc1[4] = ffma2(iB, wC.x, acc1[4]);
                    acc0[5] = ffma2(iA, wC.y, acc0[5]); acc1[5] = ffma2(iB, wC.y, acc1[5]);
                    acc0[6] = ffma2(iA, wD.x, acc0[6]); acc1[6] = ffma2(iB, wD.x, acc1[6]);
                    acc0[7] = ffma2(iA, wD.y, acc0[7]); acc1[7] = ffma2(iB, wD.y, acc1[7]);
                }
            }
        }

        #pragma unroll
        for (int pix = 0; pix < 2; ++pix) {
            const u64* acc = pix ? acc1 : acc0;
            const int p = y * HW + (pix ? x1 : x0);
            if (g <= 1) {
                __nv_bfloat16* dst = (g == 0 ? g_Qs : g_Ks)
                                   + (size_t)(b * NPIX + p) * 64 + (co0 & 31);
                #pragma unroll
                for (int u = 0; u < 8; ++u) {
                    float2 v = funpack2(acc[u]);
                    __nv_bfloat162 h = __floats2bfloat162_rn(v.x, v.y);
                    __nv_bfloat162 l = __floats2bfloat162_rn(
                        v.x - __bfloat162float(h.x), v.y - __bfloat162float(h.y));
                    *reinterpret_cast<__nv_bfloat162*>(dst + 2 * u)      = h;
                    *reinterpret_cast<__nv_bfloat162*>(dst + 32 + 2 * u) = l;
                }
            } else {
                __nv_bfloat16* dst = g_V + (size_t)(b * NPIX + p) * 64 + (co0 - 64);
                #pragma unroll
                for (int u = 0; u < 8; ++u) {
                    float2 v = funpack2(acc[u]);
                    *reinterpret_cast<__nv_bfloat162*>(dst + 2 * u) =
                        __floats2bfloat162_rn(v.x, v.y);
                }
            }
        }
    }
}

// ---------------------------------------------------------------------------
// Tensor-core flash attention. 64 threads = 2 warps; warp w owns 16 queries.
// 512 CTAs (32 queries each) -> ~6 resident CTAs/SM, desynced chunk loops.
// SMEM rows padded to 144B (conflict-free ldmatrix):
//   Qs[32][72]bf16 @0 | K0@4608 K1@13824 | V0@23040 V1@32256 ([64][72]bf16)
//   Of[32][65]f32 @4608 (epilogue reuse of K0)
// ---------------------------------------------------------------------------
#define SM_Q  0
#define SM_K0 4608
#define SM_V0 23040
#define ATTN_SMEM 41472
#define EXP2_BIAS 51.0f

__global__ __launch_bounds__(64)
void attn_kernel(const float* __restrict__ A1C, float* __restrict__ out) {
    extern __shared__ __align__(16) char sm[];
    char* Qs  = sm + SM_Q;
    char* Kb0 = sm + SM_K0;
    char* Vb0 = sm + SM_V0;
    float* Of = reinterpret_cast<float*>(sm + SM_K0);

    const int rb   = blockIdx.x;
    const int b    = blockIdx.y;
    const int tid  = threadIdx.x;
    const int lane = tid & 31;
    const int w    = tid >> 5;
    const int q0   = rb * 32;
    const char* gQ = (const char*)(g_Qs + (size_t)(b * NPIX + q0) * 64);
    const char* gK = (const char*)(g_Ks + (size_t)b * NPIX * 64);
    const char* gV = (const char*)(g_V  + (size_t)b * NPIX * 64);

    // ---- prologue: Q (32 rows) + K(0) + V(0) (64 rows each) -------------------
    for (int f = tid; f < 256; f += 64) {
        int r = f >> 3, s = (f & 7) * 16;
        cp_async16(Qs + r * 144 + s, gQ + r * 128 + s);
    }
    for (int f = tid; f < 512; f += 64) {
        int r = f >> 3, s = (f & 7) * 16;
        cp_async16(Kb0 + r * 144 + s, gK + r * 128 + s);
        cp_async16(Vb0 + r * 144 + s, gV + r * 128 + s);
    }
    CP_COMMIT();
    CP_WAIT0();
    __syncthreads();

    // ---- Q fragments (resident in registers for the whole kernel) ------------
    const u32 qrow  = w * 16 + ((lane >> 3) & 1) * 8 + (lane & 7);
    const u32 qcol8 = (lane >> 4) * 8;
    const u32 qbase = (u32)__cvta_generic_to_shared(Qs) + qrow * 144;
    u32 Ah[2][4], Al[2][4];
    ldsm4(Ah[0], qbase + (0  + qcol8) * 2);
    ldsm4(Ah[1], qbase + (16 + qcol8) * 2);
    ldsm4(Al[0], qbase + (32 + qcol8) * 2);
    ldsm4(Al[1], qbase + (48 + qcol8) * 2);

    // per-thread ldmatrix offsets for K and V (relative to buffer base)
    const u32 koff = (lane & 7) * 144 + (((lane >> 3) & 1) * 8 + (lane >> 4) * 16) * 2;
    const u32 voff = (((lane >> 3) & 1) * 8 + (lane & 7)) * 144 + (lane >> 4) * 16;

    float o[8][4] = {};
    float lsum0 = 0.f, lsum1 = 0.f;

    for (int kb = 0; kb < 64; ++kb) {
        const int buf = kb & 1;
        if (kb > 0) {
            CP_WAIT0();
            __syncthreads();
        }
        if (kb < 63) {
            const char* gKn = gK + (size_t)(kb + 1) * 64 * 128;
            const char* gVn = gV + (size_t)(kb + 1) * 64 * 128;
            char* Kn = Kb0 + (buf ^ 1) * 9216;
            char* Vn = Vb0 + (buf ^ 1) * 9216;
            for (int f = tid; f < 512; f += 64) {
                int r = f >> 3, s = (f & 7) * 16;
                cp_async16(Kn + r * 144 + s, gKn + r * 128 + s);
                cp_async16(Vn + r * 144 + s, gVn + r * 128 + s);
            }
        }
        CP_COMMIT();

        // ---- S = Q^T K (3-way bf16 split, fp32 accum) ------------------------
        const u32 kbase = (u32)__cvta_generic_to_shared(Kb0 + buf * 9216) + koff;
        float c[8][4] = {};
        #pragma unroll
        for (int nt = 0; nt < 8; ++nt) {
            u32 bh[4], bl[4];
            u32 ra = kbase + nt * 8 * 144;
            ldsm4(bh, ra);
            ldsm4(bl, ra + 64);
            mma_bf16(c[nt][0], c[nt][1], c[nt][2], c[nt][3],
                     Ah[0][0], Ah[0][1], Ah[0][2], Ah[0][3], bh[0], bh[1]);
            mma_bf16(c[nt][0], c[nt][1], c[nt][2], c[nt][3],
                     Ah[1][0], Ah[1][1], Ah[1][2], Ah[1][3], bh[2], bh[3]);
            mma_bf16(c[nt][0], c[nt][1], c[nt][2], c[nt][3],
                     Ah[0][0], Ah[0][1], Ah[0][2], Ah[0][3], bl[0], bl[1]);
            mma_bf16(c[nt][0], c[nt][1], c[nt][2], c[nt][3],
                     Ah[1][0], Ah[1][1], Ah[1][2], Ah[1][3], bl[2], bl[3]);
            mma_bf16(c[nt][0], c[nt][1], c[nt][2], c[nt][3],
                     Al[0][0], Al[0][1], Al[0][2], Al[0][3], bh[0], bh[1]);
            mma_bf16(c[nt][0], c[nt][1], c[nt][2], c[nt][3],
                     Al[1][0], Al[1][1], Al[1][2], Al[1][3], bh[2], bh[3]);
        }

        // ---- softmax (base-2, fixed bias) + P split to bf16 A-frags ----------
        u32 Ph[4][4], Pl[4][4];
        #pragma unroll
        for (int nt = 0; nt < 8; ++nt) {
            float e0 = ex2f(c[nt][0] - EXP2_BIAS);
            float e1 = ex2f(c[nt][1] - EXP2_BIAS);
            float e2 = ex2f(c[nt][2] - EXP2_BIAS);
            float e3 = ex2f(c[nt][3] - EXP2_BIAS);
            lsum0 += e0 + e1;
            lsum1 += e2 + e3;
            __nv_bfloat162 h01 = __floats2bfloat162_rn(e0, e1);
            __nv_bfloat162 h23 = __floats2bfloat162_rn(e2, e3);
            __nv_bfloat162 l01 = __floats2bfloat162_rn(
                e0 - __bfloat162float(h01.x), e1 - __bfloat162float(h01.y));
            __nv_bfloat162 l23 = __floats2bfloat162_rn(
                e2 - __bfloat162float(h23.x), e3 - __bfloat162float(h23.y));
            int kt = nt >> 1, q = (nt & 1) * 2;
            Ph[kt][q]     = bf2u(h01);
            Ph[kt][q + 1] = bf2u(h23);
            Pl[kt][q]     = bf2u(l01);
            Pl[kt][q + 1] = bf2u(l23);
        }

        // ---- O += P V (P split, V single bf16) --------------------------------
        const u32 vbase = (u32)__cvta_generic_to_shared(Vb0 + buf * 9216) + voff;
        #pragma unroll
        for (int kt = 0; kt < 4; ++kt) {
            #pragma unroll
            for (int cb = 0; cb < 4; ++cb) {
                u32 vr[4];
                ldsm4t(vr, vbase + kt * 16 * 144 + cb * 32);
                float* oa = o[2 * cb];
                float* ob = o[2 * cb + 1];
                mma_bf16(oa[0], oa[1], oa[2], oa[3],
                         Ph[kt][0], Ph[kt][1], Ph[kt][2], Ph[kt][3], vr[0], vr[1]);
                mma_bf16(oa[0], oa[1], oa[2], oa[3],
                         Pl[kt][0], Pl[kt][1], Pl[kt][2], Pl[kt][3], vr[0], vr[1]);
                mma_bf16(ob[0], ob[1], ob[2], ob[3],
                         Ph[kt][0], Ph[kt][1], Ph[kt][2], Ph[kt][3], vr[2], vr[3]);
                mma_bf16(ob[0], ob[1], ob[2], ob[3],
                         Pl[kt][0], Pl[kt][1], Pl[kt][2], Pl[kt][3], vr[2], vr[3]);
            }
        }
    }

    // ---- l reduction across the quad (cols live on 4 lanes) ------------------
    lsum0 += __shfl_xor_sync(0xffffffffu, lsum0, 1);
    lsum0 += __shfl_xor_sync(0xffffffffu, lsum0, 2);
    lsum1 += __shfl_xor_sync(0xffffffffu, lsum1, 1);
    lsum1 += __shfl_xor_sync(0xffffffffu, lsum1, 2);

    __syncthreads();   // all PV reads done before Of overwrites K buffer

    // ---- stage O/l into SMEM [row][ch] (stride 65) ----------------------------
    {
        float inv0 = 1.f / lsum0, inv1 = 1.f / lsum1;
        int r0 = w * 16 + (lane >> 2);
        int cc = (lane & 3) * 2;
        #pragma unroll
        for (int ct = 0; ct < 8; ++ct) {
            Of[r0 * 65 + ct * 8 + cc]           = o[ct][0] * inv0;
            Of[r0 * 65 + ct * 8 + cc + 1]       = o[ct][1] * inv0;
            Of[(r0 + 8) * 65 + ct * 8 + cc]     = o[ct][2] * inv1;
            Of[(r0 + 8) * 65 + ct * 8 + cc + 1] = o[ct][3] * inv1;
        }
    }
    __syncthreads();

    // ---- coalesced transpose-out + residual: thread = channel, 32 pixels ------
    {
        int ch = tid;
        int gbase = (b * 64 + ch) * NPIX + q0;
        #pragma unroll
        for (int ww = 0; ww < 32; ww += 4) {
            float4 r = *reinterpret_cast<const float4*>(A1C + gbase + ww);
            float4 oo;
            oo.x = Of[(ww + 0) * 65 + ch] + r.x;
            oo.y = Of[(ww + 1) * 65 + ch] + r.y;
            oo.z = Of[(ww + 2) * 65 + ch] + r.z;
            oo.w = Of[(ww + 3) * 65 + ch] + r.w;
            *reinterpret_cast<float4*>(out + gbase + ww) = oo;
        }
    }
}

// ---------------------------------------------------------------------------
extern "C" void kernel_launch(void* const* d_in, const int* in_sizes, int n_in,
                              void* d_out, int out_size) {
    const float* A1B = (const float*)d_in[0];
    const float* A1C = (const float*)d_in[1];
    const float* w1  = (const float*)d_in[2];
    const float* b1  = (const float*)d_in[3];
    const float* w2  = (const float*)d_in[4];
    const float* b2  = (const float*)d_in[5];
    const float* w3  = (const float*)d_in[6];
    const float* b3  = (const float*)d_in[7];
    float* out = (float*)d_out;

    cudaFuncSetAttribute(conv_kernel, cudaFuncAttributeMaxDynamicSharedMemorySize, CONV_SMEM);
    cudaFuncSetAttribute(attn_kernel, cudaFuncAttributeMaxDynamicSharedMemorySize, ATTN_SMEM);

    pack_kernel<<<288, 256>>>(w1, b1, w2, b2, w3, b3);
    conv_kernel<<<dim3(HW, NB), 128, CONV_SMEM>>>(A1B, A1C);
    attn_kernel<<<dim3(NPIX / 32, NB), 64, ATTN_SMEM>>>(A1C, out);
}

// round 12
// speedup vs baseline: 1.0682x; 1.0682x over previous
#include <cuda_runtime.h>
#include <cuda_bf16.h>
#include <cuda_fp16.h>

// ---------------------------------------------------------------------------
// BSAM self-attention via mma.sync (bf16 QK, fp16 PV), fp32 conv front.
//   Q = conv3x3(A1_B, w1*log2e, b1*log2e) -> g_Qs [b][p][hi32|lo32] bf16
//   K = conv3x3(A1_C, w2,b2)              -> g_Ks [b][p][hi32|lo32] bf16
//   V = conv3x3(A1_C, w3,b3)              -> g_V  [b][p][64] fp16
//   S = Q.K (3-way bf16 split); online per-row max softmax (base-2);
//   P fp16 single; O += P V (fp16 MMA). out = (O/l)^T + A1_C
// R11: PV MMAs halved (64->32/warp/chunk) via fp16 P + online max.
// ---------------------------------------------------------------------------

#define NB   4
#define NC   64
#define HW   64
#define NPIX 4096

typedef unsigned long long u64;
typedef unsigned u32;

__device__ __align__(16) __nv_bfloat16 g_Qs[NB * NPIX * 64];
__device__ __align__(16) __nv_bfloat16 g_Ks[NB * NPIX * 64];
__device__ __align__(16) __half        g_V [NB * NPIX * 64];
__device__ __align__(16) float g_wpack[64 * 9 * 128];
__device__ __align__(16) float g_bias[128];

// ---- packed f32x2 helpers (conv) -------------------------------------------
__device__ __forceinline__ u64 ffma2(u64 a, u64 b, u64 c) {
    u64 d; asm("fma.rn.f32x2 %0, %1, %2, %3;" : "=l"(d) : "l"(a), "l"(b), "l"(c));
    return d;
}
__device__ __forceinline__ u64 fpack2(float lo, float hi) {
    u64 d; asm("mov.b64 %0, {%1, %2};" : "=l"(d) : "f"(lo), "f"(hi));
    return d;
}
__device__ __forceinline__ float2 funpack2(u64 v) {
    float2 r; asm("mov.b64 {%0, %1}, %2;" : "=f"(r.x), "=f"(r.y) : "l"(v));
    return r;
}
__device__ __forceinline__ float ex2f(float x) {
    float y; asm("ex2.approx.f32 %0, %1;" : "=f"(y) : "f"(x));
    return y;
}

// ---- cp.async / mma / ldmatrix ----------------------------------------------
__device__ __forceinline__ void cp_async16(void* sdst, const void* gsrc) {
    u32 sa = (u32)__cvta_generic_to_shared(sdst);
    asm volatile("cp.async.cg.shared.global [%0], [%1], 16;" :: "r"(sa), "l"(gsrc));
}
#define CP_COMMIT() asm volatile("cp.async.commit_group;")
#define CP_WAIT0()  asm volatile("cp.async.wait_group 0;")

__device__ __forceinline__ void mma_bf16(float& c0, float& c1, float& c2, float& c3,
                                         u32 a0, u32 a1, u32 a2, u32 a3,
                                         u32 b0, u32 b1) {
    asm volatile(
        "mma.sync.aligned.m16n8k16.row.col.f32.bf16.bf16.f32 "
        "{%0,%1,%2,%3}, {%4,%5,%6,%7}, {%8,%9}, {%0,%1,%2,%3};"
        : "+f"(c0), "+f"(c1), "+f"(c2), "+f"(c3)
        : "r"(a0), "r"(a1), "r"(a2), "r"(a3), "r"(b0), "r"(b1));
}
__device__ __forceinline__ void mma_f16(float& c0, float& c1, float& c2, float& c3,
                                        u32 a0, u32 a1, u32 a2, u32 a3,
                                        u32 b0, u32 b1) {
    asm volatile(
        "mma.sync.aligned.m16n8k16.row.col.f32.f16.f16.f32 "
        "{%0,%1,%2,%3}, {%4,%5,%6,%7}, {%8,%9}, {%0,%1,%2,%3};"
        : "+f"(c0), "+f"(c1), "+f"(c2), "+f"(c3)
        : "r"(a0), "r"(a1), "r"(a2), "r"(a3), "r"(b0), "r"(b1));
}
__device__ __forceinline__ void ldsm4(u32* r, u32 saddr) {
    asm volatile("ldmatrix.sync.aligned.m8n8.x4.shared.b16 {%0,%1,%2,%3}, [%4];"
        : "=r"(r[0]), "=r"(r[1]), "=r"(r[2]), "=r"(r[3]) : "r"(saddr));
}
__device__ __forceinline__ void ldsm4t(u32* r, u32 saddr) {
    asm volatile("ldmatrix.sync.aligned.m8n8.x4.trans.shared.b16 {%0,%1,%2,%3}, [%4];"
        : "=r"(r[0]), "=r"(r[1]), "=r"(r[2]), "=r"(r[3]) : "r"(saddr));
}
__device__ __forceinline__ u32 bf2u(__nv_bfloat162 h) {
    return *reinterpret_cast<u32*>(&h);
}
__device__ __forceinline__ u32 h2u(__half2 h) {
    return *reinterpret_cast<u32*>(&h);
}

// ---------------------------------------------------------------------------
// Weight repack. co 0..31 = w1*log2e (Q), 32..63 = w2, 64..127 = w3
// ---------------------------------------------------------------------------
#define LOG2E 1.4426950408889634f

__global__ void pack_kernel(const float* __restrict__ w1, const float* __restrict__ b1,
                            const float* __restrict__ w2, const float* __restrict__ b2,
                            const float* __restrict__ w3, const float* __restrict__ b3) {
    int idx = blockIdx.x * 256 + threadIdx.x;
    if (idx < 128)
        g_bias[idx] = (idx < 32) ? b1[idx] * LOG2E
                    : (idx < 64) ? b2[idx - 32] : b3[idx - 64];
    if (idx < 64 * 9 * 128) {
        int co = idx & 127;
        int t  = idx >> 7;
        int ci = t / 9;
        int k  = t % 9;
        float v;
        if (co < 32)       v = w1[(co * 64 + ci) * 9 + k] * LOG2E;
        else if (co < 64)  v = w2[((co - 32) * 64 + ci) * 9 + k];
        else               v = w3[((co - 64) * 64 + ci) * 9 + k];
        g_wpack[idx] = v;
    }
}

// ---------------------------------------------------------------------------
// Conv: block=(row y, batch b), 128 thr = 32 x-lanes x 4 groups, 2 pixels/thr.
// Q/K bf16 split [hi32|lo32]; V single fp16.
// ---------------------------------------------------------------------------
#define CONV_SMEM (2 * 64 * 3 * 66 * 4)

__global__ __launch_bounds__(128)
void conv_kernel(const float* __restrict__ A1B, const float* __restrict__ A1C) {
    extern __shared__ float smem[];
    float* sB = smem;
    float* sC = smem + 64 * 3 * 66;

    const int y   = blockIdx.x;
    const int b   = blockIdx.y;
    const int tid = threadIdx.x;

    for (int idx = tid; idx < 64 * 3 * 66; idx += 128) {
        int ci  = idx / 198;
        int rem = idx % 198;
        int r   = rem / 66;
        int xx  = rem % 66;
        int yy  = y + r - 1;
        int x   = xx - 1;
        bool ok = (yy >= 0) && (yy < HW) && (x >= 0) && (x < HW);
        float vb = 0.f, vc = 0.f;
        if (ok) {
            int gi = ((b * 64 + ci) * HW + yy) * HW + x;
            vb = __ldg(A1B + gi);
            vc = __ldg(A1C + gi);
        }
        sB[idx] = vb;
        sC[idx] = vc;
    }
    __syncthreads();

    const int x0 = tid & 31;
    const int x1 = x0 + 32;
    const int g  = tid >> 5;
    const float* sIn = (g == 0) ? sB : sC;

    #pragma unroll
    for (int pass = 0; pass < 2; ++pass) {
        const int co0 = g * 32 + pass * 16;
        const u64* bp = reinterpret_cast<const u64*>(g_bias + co0);
        u64 acc0[8], acc1[8];
        #pragma unroll
        for (int u = 0; u < 8; ++u) { acc0[u] = bp[u]; acc1[u] = bp[u]; }

        for (int ci = 0; ci < 64; ++ci) {
            #pragma unroll
            for (int dy = 0; dy < 3; ++dy) {
                const float* row = sIn + (ci * 3 + dy) * 66;
                float a0 = row[x0], a1 = row[x0 + 1], a2 = row[x0 + 2];
                float c0 = row[x1], c1 = row[x1 + 1], c2 = row[x1 + 2];
                #pragma unroll
                for (int dx = 0; dx < 3; ++dx) {
                    float ivA = (dx == 0) ? a0 : (dx == 1) ? a1 : a2;
                    float ivB = (dx == 0) ? c0 : (dx == 1) ? c1 : c2;
                    u64 iA = fpack2(ivA, ivA);
                    u64 iB = fpack2(ivB, ivB);
                    const ulonglong2* wq = reinterpret_cast<const ulonglong2*>(
                        g_wpack + ((ci * 3 + dy) * 3 + dx) * 128 + co0);
                    ulonglong2 wA = __ldg(wq + 0);
                    ulonglong2 wB = __ldg(wq + 1);
                    ulonglong2 wC = __ldg(wq + 2);
                    ulonglong2 wD = __ldg(wq + 3);
                    acc0[0] = ffma2(iA, wA.x, acc0[0]); acc1[0] = ffma2(iB, wA.x, acc1[0]);
                    acc0[1] = ffma2(iA, wA.y, acc0[1]); acc1[1] = ffma2(iB, wA.y, acc1[1]);
                    acc0[2] = ffma2(iA, wB.x, acc0[2]); acc1[2] = ffma2(iB, wB.x, acc1[2]);
                    acc0[3] = ffma2(iA, wB.y, acc0[3]); acc1[3] = ffma2(iB, wB.y, acc1[3]);
                    acc0[4] = ffma2(iA, wC.x, acc0[4]); acc1[4] = ffma2(iB, wC.x, acc1[4]);
                    acc0[5] = ffma2(iA, wC.y, acc0[5]); acc1[5] = ffma2(iB, wC.y, acc1[5]);
                    acc0[6] = ffma2(iA, wD.x, acc0[6]); acc1[6] = ffma2(iB, wD.x, acc1[6]);
                    acc0[7] = ffma2(iA, wD.y, acc0[7]); acc1[7] = ffma2(iB, wD.y, acc1[7]);
                }
            }
        }

        #pragma unroll
        for (int pix = 0; pix < 2; ++pix) {
            const u64* acc = pix ? acc1 : acc0;
            const int p = y * HW + (pix ? x1 : x0);
            if (g <= 1) {
                __nv_bfloat16* dst = (g == 0 ? g_Qs : g_Ks)
                                   + (size_t)(b * NPIX + p) * 64 + (co0 & 31);
                #pragma unroll
                for (int u = 0; u < 8; ++u) {
                    float2 v = funpack2(acc[u]);
                    __nv_bfloat162 h = __floats2bfloat162_rn(v.x, v.y);
                    __nv_bfloat162 l = __floats2bfloat162_rn(
                        v.x - __bfloat162float(h.x), v.y - __bfloat162float(h.y));
                    *reinterpret_cast<__nv_bfloat162*>(dst + 2 * u)      = h;
                    *reinterpret_cast<__nv_bfloat162*>(dst + 32 + 2 * u) = l;
                }
            } else {
                __half* dst = g_V + (size_t)(b * NPIX + p) * 64 + (co0 - 64);
                #pragma unroll
                for (int u = 0; u < 8; ++u) {
                    float2 v = funpack2(acc[u]);
                    *reinterpret_cast<__half2*>(dst + 2 * u) =
                        __floats2half2_rn(v.x, v.y);
                }
            }
        }
    }
}

// ---------------------------------------------------------------------------
// Tensor-core flash attention. 128 threads = 4 warps, warp w owns 16 queries.
// Online per-row max softmax; P single fp16; V fp16.
// SMEM rows padded to 144B (conflict-free ldmatrix):
//   Qs[64][72]bf16 @0 | K0@9216 K1@18432 | V0@27648 V1@36864 ([64][72] 16-bit)
//   Of[64][65]f32 @9216 (epilogue reuse)
// ---------------------------------------------------------------------------
#define ATTN_SMEM (5 * 9216)

__global__ __launch_bounds__(128)
void attn_kernel(const float* __restrict__ A1C, float* __restrict__ out) {
    extern __shared__ __align__(16) char sm[];
    char* Qs  = sm;
    char* Kb0 = sm + 9216;
    char* Vb0 = sm + 27648;
    float* Of = reinterpret_cast<float*>(sm + 9216);

    const int rb   = blockIdx.x;
    const int b    = blockIdx.y;
    const int tid  = threadIdx.x;
    const int lane = tid & 31;
    const int w    = tid >> 5;
    const int q0   = rb * 64;
    const char* gQ = (const char*)(g_Qs + (size_t)(b * NPIX + q0) * 64);
    const char* gK = (const char*)(g_Ks + (size_t)b * NPIX * 64);
    const char* gV = (const char*)(g_V  + (size_t)b * NPIX * 64);

    // ---- prologue: Q + K(0) + V(0) -------------------------------------------
    for (int f = tid; f < 512; f += 128) {
        int r = f >> 3, s = (f & 7) * 16;
        cp_async16(Qs  + r * 144 + s, gQ + r * 128 + s);
        cp_async16(Kb0 + r * 144 + s, gK + r * 128 + s);
        cp_async16(Vb0 + r * 144 + s, gV + r * 128 + s);
    }
    CP_COMMIT();
    CP_WAIT0();
    __syncthreads();

    // ---- Q fragments (resident in registers for the whole kernel) ------------
    const u32 qrow  = w * 16 + ((lane >> 3) & 1) * 8 + (lane & 7);
    const u32 qcol8 = (lane >> 4) * 8;
    const u32 qbase = (u32)__cvta_generic_to_shared(Qs) + qrow * 144;
    u32 Ah[2][4], Al[2][4];
    ldsm4(Ah[0], qbase + (0  + qcol8) * 2);
    ldsm4(Ah[1], qbase + (16 + qcol8) * 2);
    ldsm4(Al[0], qbase + (32 + qcol8) * 2);
    ldsm4(Al[1], qbase + (48 + qcol8) * 2);

    // per-thread ldmatrix offsets for K and V (relative to buffer base)
    const u32 koff = (lane & 7) * 144 + (((lane >> 3) & 1) * 8 + (lane >> 4) * 16) * 2;
    const u32 voff = (((lane >> 3) & 1) * 8 + (lane & 7)) * 144 + (lane >> 4) * 16;

    float o[8][4] = {};
    float lsum0 = 0.f, lsum1 = 0.f;
    float m0 = -1e30f, m1 = -1e30f;

    for (int kb = 0; kb < 64; ++kb) {
        const int buf = kb & 1;
        if (kb > 0) {
            CP_WAIT0();
            __syncthreads();
        }
        if (kb < 63) {
            const char* gKn = gK + (size_t)(kb + 1) * 64 * 128;
            const char* gVn = gV + (size_t)(kb + 1) * 64 * 128;
            char* Kn = Kb0 + (buf ^ 1) * 9216;
            char* Vn = Vb0 + (buf ^ 1) * 9216;
            for (int f = tid; f < 512; f += 128) {
                int r = f >> 3, s = (f & 7) * 16;
                cp_async16(Kn + r * 144 + s, gKn + r * 128 + s);
                cp_async16(Vn + r * 144 + s, gVn + r * 128 + s);
            }
        }
        CP_COMMIT();

        // ---- S = Q^T K (3-way bf16 split, fp32 accum) ------------------------
        const u32 kbase = (u32)__cvta_generic_to_shared(Kb0 + buf * 9216) + koff;
        float c[8][4] = {};
        #pragma unroll
        for (int nt = 0; nt < 8; ++nt) {
            u32 bh[4], bl[4];
            u32 ra = kbase + nt * 8 * 144;
            ldsm4(bh, ra);
            ldsm4(bl, ra + 64);
            mma_bf16(c[nt][0], c[nt][1], c[nt][2], c[nt][3],
                     Ah[0][0], Ah[0][1], Ah[0][2], Ah[0][3], bh[0], bh[1]);
            mma_bf16(c[nt][0], c[nt][1], c[nt][2], c[nt][3],
                     Ah[1][0], Ah[1][1], Ah[1][2], Ah[1][3], bh[2], bh[3]);
            mma_bf16(c[nt][0], c[nt][1], c[nt][2], c[nt][3],
                     Ah[0][0], Ah[0][1], Ah[0][2], Ah[0][3], bl[0], bl[1]);
            mma_bf16(c[nt][0], c[nt][1], c[nt][2], c[nt][3],
                     Ah[1][0], Ah[1][1], Ah[1][2], Ah[1][3], bl[2], bl[3]);
            mma_bf16(c[nt][0], c[nt][1], c[nt][2], c[nt][3],
                     Al[0][0], Al[0][1], Al[0][2], Al[0][3], bh[0], bh[1]);
            mma_bf16(c[nt][0], c[nt][1], c[nt][2], c[nt][3],
                     Al[1][0], Al[1][1], Al[1][2], Al[1][3], bh[2], bh[3]);
        }

        // ---- online per-row max (rows live across a quad: shfl 1,2) ----------
        float mx0 = -1e30f, mx1 = -1e30f;
        #pragma unroll
        for (int nt = 0; nt < 8; ++nt) {
            mx0 = fmaxf(mx0, fmaxf(c[nt][0], c[nt][1]));
            mx1 = fmaxf(mx1, fmaxf(c[nt][2], c[nt][3]));
        }
        mx0 = fmaxf(mx0, __shfl_xor_sync(0xffffffffu, mx0, 1));
        mx0 = fmaxf(mx0, __shfl_xor_sync(0xffffffffu, mx0, 2));
        mx1 = fmaxf(mx1, __shfl_xor_sync(0xffffffffu, mx1, 1));
        mx1 = fmaxf(mx1, __shfl_xor_sync(0xffffffffu, mx1, 2));
        float mn0 = fmaxf(m0, mx0), mn1 = fmaxf(m1, mx1);
        if (mn0 > m0 || mn1 > m1) {
            float a0 = ex2f(m0 - mn0), a1 = ex2f(m1 - mn1);
            lsum0 *= a0; lsum1 *= a1;
            #pragma unroll
            for (int ct = 0; ct < 8; ++ct) {
                o[ct][0] *= a0; o[ct][1] *= a0;
                o[ct][2] *= a1; o[ct][3] *= a1;
            }
            m0 = mn0; m1 = mn1;
        }

        // ---- softmax (base-2, per-row max) + P fp16 A-frags -------------------
        u32 Ph[4][4];
        #pragma unroll
        for (int nt = 0; nt < 8; ++nt) {
            float e0 = ex2f(c[nt][0] - m0);
            float e1 = ex2f(c[nt][1] - m0);
            float e2 = ex2f(c[nt][2] - m1);
            float e3 = ex2f(c[nt][3] - m1);
            lsum0 += e0 + e1;
            lsum1 += e2 + e3;
            int kt = nt >> 1, q = (nt & 1) * 2;
            Ph[kt][q]     = h2u(__floats2half2_rn(e0, e1));
            Ph[kt][q + 1] = h2u(__floats2half2_rn(e2, e3));
        }

        // ---- O += P V (fp16 MMA, 2 per tile) ----------------------------------
        const u32 vbase = (u32)__cvta_generic_to_shared(Vb0 + buf * 9216) + voff;
        #pragma unroll
        for (int kt = 0; kt < 4; ++kt) {
            #pragma unroll
            for (int cb = 0; cb < 4; ++cb) {
                u32 vr[4];
                ldsm4t(vr, vbase + kt * 16 * 144 + cb * 32);
                float* oa = o[2 * cb];
                float* ob = o[2 * cb + 1];
                mma_f16(oa[0], oa[1], oa[2], oa[3],
                        Ph[kt][0], Ph[kt][1], Ph[kt][2], Ph[kt][3], vr[0], vr[1]);
                mma_f16(ob[0], ob[1], ob[2], ob[3],
                        Ph[kt][0], Ph[kt][1], Ph[kt][2], Ph[kt][3], vr[2], vr[3]);
            }
        }
    }

    // ---- l reduction across the quad (cols live on 4 lanes) ------------------
    lsum0 += __shfl_xor_sync(0xffffffffu, lsum0, 1);
    lsum0 += __shfl_xor_sync(0xffffffffu, lsum0, 2);
    lsum1 += __shfl_xor_sync(0xffffffffu, lsum1, 1);
    lsum1 += __shfl_xor_sync(0xffffffffu, lsum1, 2);

    __syncthreads();   // all PV reads done before Of overwrites K/V buffers

    // ---- stage O/l into SMEM [row][ch] (stride 65) ----------------------------
    {
        float inv0 = 1.f / lsum0, inv1 = 1.f / lsum1;
        int r0 = w * 16 + (lane >> 2);
        int cc = (lane & 3) * 2;
        #pragma unroll
        for (int ct = 0; ct < 8; ++ct) {
            Of[r0 * 65 + ct * 8 + cc]           = o[ct][0] * inv0;
            Of[r0 * 65 + ct * 8 + cc + 1]       = o[ct][1] * inv0;
            Of[(r0 + 8) * 65 + ct * 8 + cc]     = o[ct][2] * inv1;
            Of[(r0 + 8) * 65 + ct * 8 + cc + 1] = o[ct][3] * inv1;
        }
    }
    __syncthreads();

    // ---- coalesced transpose-out + residual -----------------------------------
    {
        int ch = tid >> 1, seg = (tid & 1) * 32;
        int gbase = (b * 64 + ch) * NPIX + q0 + seg;
        #pragma unroll
        for (int ww = 0; ww < 32; ww += 4) {
            float4 r = *reinterpret_cast<const float4*>(A1C + gbase + ww);
            float4 oo;
            oo.x = Of[(seg + ww + 0) * 65 + ch] + r.x;
            oo.y = Of[(seg + ww + 1) * 65 + ch] + r.y;
            oo.z = Of[(seg + ww + 2) * 65 + ch] + r.z;
            oo.w = Of[(seg + ww + 3) * 65 + ch] + r.w;
            *reinterpret_cast<float4*>(out + gbase + ww) = oo;
        }
    }
}

// ---------------------------------------------------------------------------
extern "C" void kernel_launch(void* const* d_in, const int* in_sizes, int n_in,
                              void* d_out, int out_size) {
    const float* A1B = (const float*)d_in[0];
    const float* A1C = (const float*)d_in[1];
    const float* w1  = (const float*)d_in[2];
    const float* b1  = (const float*)d_in[3];
    const float* w2  = (const float*)d_in[4];
    const float* b2  = (const float*)d_in[5];
    const float* w3  = (const float*)d_in[6];
    const float* b3  = (const float*)d_in[7];
    float* out = (float*)d_out;

    cudaFuncSetAttribute(conv_kernel, cudaFuncAttributeMaxDynamicSharedMemorySize, CONV_SMEM);
    cudaFuncSetAttribute(attn_kernel, cudaFuncAttributeMaxDynamicSharedMemorySize, ATTN_SMEM);

    pack_kernel<<<288, 256>>>(w1, b1, w2, b2, w3, b3);
    conv_kernel<<<dim3(HW, NB), 128, CONV_SMEM>>>(A1B, A1C);
    attn_kernel<<<dim3(NPIX / 64, NB), 128, ATTN_SMEM>>>(A1C, out);
}